// round 2
// baseline (speedup 1.0000x reference)
#include <cuda_runtime.h>

#define H_DIM 10
#define N_DIM 100000
#define F_DIM 256
#define HID_DIM 512
#define C_DIM 47

// ---------------- scratch (device globals: no allocation allowed) ----------------
__device__ float g_right[(size_t)N_DIM * F_DIM];   // 102.4 MB
__device__ float g_x1[(size_t)N_DIM * HID_DIM];    // 204.8 MB  (h0 / y0 / y2)
__device__ float g_x2[(size_t)N_DIM * HID_DIM];    // 204.8 MB  (x2 / y1)
__device__ float g_x3[(size_t)N_DIM * HID_DIM];    // 204.8 MB  (x3)
__device__ float g_xout[(size_t)N_DIM * C_DIM];    // 18.8 MB

// ---------------- helpers ----------------
__device__ __forceinline__ float lrelu02(float x) { return x >= 0.f ? x : 0.2f * x; }
__device__ __forceinline__ float preluf(float x, float a) { return x >= 0.f ? x : a * x; }

__device__ __forceinline__ void ffma2(unsigned long long& acc,
                                      unsigned long long a,
                                      unsigned long long b) {
    asm("fma.rn.f32x2 %0, %1, %2, %0;" : "+l"(acc) : "l"(a), "l"(b));
}
__device__ __forceinline__ float ull_lo(unsigned long long u) {
    return __uint_as_float((unsigned)u);
}
__device__ __forceinline__ float ull_hi(unsigned long long u) {
    return __uint_as_float((unsigned)(u >> 32));
}

// ---------------- fused attention: one pass over features ----------------
// warp per n. Each lane holds 8 feature floats per h (2x float4), all H rows in regs.
__global__ __launch_bounds__(128)
void attn_kernel(const float* __restrict__ feat,
                 const float* __restrict__ wa,
                 const float* __restrict__ ba_p,
                 float* __restrict__ right)
{
    const int warp = threadIdx.x >> 5;
    const int lane = threadIdx.x & 31;
    const int n = blockIdx.x * 4 + warp;
    if (n >= N_DIM) return;

    const float4* wa4 = reinterpret_cast<const float4*>(wa);
    const float4 wl_a = wa4[lane];
    const float4 wl_b = wa4[32 + lane];
    const float4 wr_a = wa4[64 + lane];
    const float4 wr_b = wa4[96 + lane];
    const float ba = *ba_p;

    float4 fa[H_DIM], fb[H_DIM];
    float xl[H_DIM], xr[H_DIM];

#pragma unroll
    for (int h = 0; h < H_DIM; ++h) {
        const float4* f4 = reinterpret_cast<const float4*>(
            feat + ((size_t)h * N_DIM + (size_t)n) * F_DIM);
        fa[h] = f4[lane];
        fb[h] = f4[32 + lane];
        float dl = fa[h].x * wl_a.x + fa[h].y * wl_a.y + fa[h].z * wl_a.z + fa[h].w * wl_a.w
                 + fb[h].x * wl_b.x + fb[h].y * wl_b.y + fb[h].z * wl_b.z + fb[h].w * wl_b.w;
        float dr = fa[h].x * wr_a.x + fa[h].y * wr_a.y + fa[h].z * wr_a.z + fa[h].w * wr_a.w
                 + fb[h].x * wr_b.x + fb[h].y * wr_b.y + fb[h].z * wr_b.z + fb[h].w * wr_b.w;
#pragma unroll
        for (int off = 16; off; off >>= 1) {
            dl += __shfl_xor_sync(0xffffffffu, dl, off);
            dr += __shfl_xor_sync(0xffffffffu, dr, off);
        }
        xl[h] = dl;
        xr[h] = dr;
    }

    // scalar recurrence (redundant across lanes, trivial cost)
    float sc[H_DIM];
    sc[0] = lrelu02(xl[0] + xr[0] + ba);
#pragma unroll
    for (int i = 1; i < H_DIM; ++i) {
        float mx = sc[0];
#pragma unroll
        for (int j = 1; j < i; ++j) mx = fmaxf(mx, sc[j]);
        float s = 0.f, accv = 0.f;
#pragma unroll
        for (int j = 0; j < i; ++j) {
            float e = __expf(sc[j] - mx);
            s += e;
            accv += e * xl[j];
        }
        sc[i] = lrelu02(accv / s + xr[i] + ba);
    }

    // final softmax + weighted feature sum
    float mx = sc[0];
#pragma unroll
    for (int j = 1; j < H_DIM; ++j) mx = fmaxf(mx, sc[j]);
    float s = 0.f;
    float4 ra = make_float4(0.f, 0.f, 0.f, 0.f);
    float4 rb = make_float4(0.f, 0.f, 0.f, 0.f);
#pragma unroll
    for (int h = 0; h < H_DIM; ++h) {
        float e = __expf(sc[h] - mx);
        s += e;
        ra.x += e * fa[h].x; ra.y += e * fa[h].y; ra.z += e * fa[h].z; ra.w += e * fa[h].w;
        rb.x += e * fb[h].x; rb.y += e * fb[h].y; rb.z += e * fb[h].z; rb.w += e * fb[h].w;
    }
    float inv = 1.f / s;
    ra.x *= inv; ra.y *= inv; ra.z *= inv; ra.w *= inv;
    rb.x *= inv; rb.y *= inv; rb.z *= inv; rb.w *= inv;

    float4* out4 = reinterpret_cast<float4*>(right + (size_t)n * F_DIM);
    out4[lane] = ra;
    out4[32 + lane] = rb;
}

// ---------------- fused GEMM (fp32 SIMT with packed f32x2 FMA) ----------------
// C[m,n] = epi( in(A)[m,:] @ W[:,n] )
// IN_MODE:  0 = A           1 = prelu(A,a_in)        2 = 0.5*(prelu(A,a_in)+H0)
// RES_MODE: 0 = none        1 = +R[m,n]              2 = +prelu(R[m,n],a_ep)
// HAS_BIAS: +bias[n];  EPI_PRELU: prelu(result,a_ep) at the end
template<int IN_MODE, int HAS_BIAS, int EPI_PRELU, int RES_MODE>
__global__ __launch_bounds__(256, 2)
void gemm_k(const float* __restrict__ A, const float* __restrict__ Hh,
            const float* __restrict__ W, const float* __restrict__ bias,
            const float* __restrict__ R, float* __restrict__ C,
            int M, int N, int K,
            const float* __restrict__ a_in_p, const float* __restrict__ a_ep_p)
{
    constexpr int BM = 128, BN = 64, BK = 16;
    __shared__ __align__(16) float As[2][BK][BM];
    __shared__ __align__(16) float Bs[2][BK][2 * BN];   // duplicated pairs for f32x2

    const int tid = threadIdx.x;
    const int bm = blockIdx.y * BM;
    const int bn = blockIdx.x * BN;

    float a_in = 0.f, a_ep = 0.f;
    if constexpr (IN_MODE >= 1) a_in = *a_in_p;
    if constexpr (EPI_PRELU || RES_MODE == 2) a_ep = *a_ep_p;

    // global-load assignments
    const int ar  = tid >> 2;          // A row (0..63), second at +64
    const int ak  = (tid & 3) << 2;    // A k-offset within tile
    const int bk  = tid >> 4;          // B k (0..15)
    const int bnn = (tid & 15) << 2;   // B col offset

    const bool kvec = (K & 3) == 0;
    const bool nvec = (N & 3) == 0;

    float4 aR[2];
    float4 bR;

    auto loadAB = [&](int kt) {
#pragma unroll
        for (int i = 0; i < 2; ++i) {
            int row = bm + ar + i * 64;
            int k = kt + ak;
            float4 v  = make_float4(0.f, 0.f, 0.f, 0.f);
            float4 hv = make_float4(0.f, 0.f, 0.f, 0.f);
            if (row < M && k < K) {
                const float* p = A + (size_t)row * K + k;
                if (kvec) {
                    v = *reinterpret_cast<const float4*>(p);
                } else {
                    v.x = p[0];
                    if (k + 1 < K) v.y = p[1];
                    if (k + 2 < K) v.z = p[2];
                    if (k + 3 < K) v.w = p[3];
                }
                if constexpr (IN_MODE == 2) {
                    const float* q = Hh + (size_t)row * K + k;
                    if (kvec) {
                        hv = *reinterpret_cast<const float4*>(q);
                    } else {
                        hv.x = q[0];
                        if (k + 1 < K) hv.y = q[1];
                        if (k + 2 < K) hv.z = q[2];
                        if (k + 3 < K) hv.w = q[3];
                    }
                }
            }
            if constexpr (IN_MODE == 1) {
                v.x = preluf(v.x, a_in); v.y = preluf(v.y, a_in);
                v.z = preluf(v.z, a_in); v.w = preluf(v.w, a_in);
            } else if constexpr (IN_MODE == 2) {
                v.x = 0.5f * (preluf(v.x, a_in) + hv.x);
                v.y = 0.5f * (preluf(v.y, a_in) + hv.y);
                v.z = 0.5f * (preluf(v.z, a_in) + hv.z);
                v.w = 0.5f * (preluf(v.w, a_in) + hv.w);
            }
            aR[i] = v;
        }
        {
            int k = kt + bk;
            int n = bn + bnn;
            float4 v = make_float4(0.f, 0.f, 0.f, 0.f);
            if (k < K && n < N) {
                const float* p = W + (size_t)k * N + n;
                if (nvec) {
                    v = *reinterpret_cast<const float4*>(p);
                } else {
                    v.x = p[0];
                    if (n + 1 < N) v.y = p[1];
                    if (n + 2 < N) v.z = p[2];
                    if (n + 3 < N) v.w = p[3];
                }
            }
            bR = v;
        }
    };

    auto stage = [&](int buf) {
#pragma unroll
        for (int i = 0; i < 2; ++i) {
            int m = ar + i * 64;
            As[buf][ak + 0][m] = aR[i].x;
            As[buf][ak + 1][m] = aR[i].y;
            As[buf][ak + 2][m] = aR[i].z;
            As[buf][ak + 3][m] = aR[i].w;
        }
        float* d = &Bs[buf][bk][bnn << 1];
        d[0] = bR.x; d[1] = bR.x; d[2] = bR.y; d[3] = bR.y;
        d[4] = bR.z; d[5] = bR.z; d[6] = bR.w; d[7] = bR.w;
    };

    const int ty = tid >> 4;   // 0..15 -> rows bm + ty*8 .. +7
    const int tx = tid & 15;   // 0..15 -> cols bn + tx*4 .. +3

    unsigned long long acc[4][4];
#pragma unroll
    for (int p = 0; p < 4; ++p)
#pragma unroll
        for (int j = 0; j < 4; ++j) acc[p][j] = 0ull;

    const int tiles = (K + BK - 1) / BK;
    loadAB(0);
    stage(0);
    __syncthreads();

    int buf = 0;
    for (int t = 0; t < tiles; ++t) {
        const bool more = (t + 1 < tiles);
        if (more) loadAB((t + 1) * BK);
#pragma unroll
        for (int k = 0; k < BK; ++k) {
            // LDS.128 paths: 2 vec loads for A (8 rows), 2 for B (4 dup'd cols)
            const ulonglong2* ap =
                reinterpret_cast<const ulonglong2*>(&As[buf][k][ty << 3]);
            const ulonglong2* bp =
                reinterpret_cast<const ulonglong2*>(&Bs[buf][k][tx << 3]);
            ulonglong2 aA = ap[0];
            ulonglong2 aB = ap[1];
            ulonglong2 bA = bp[0];
            ulonglong2 bB = bp[1];
            unsigned long long av0 = aA.x, av1 = aA.y, av2 = aB.x, av3 = aB.y;
            unsigned long long bv0 = bA.x, bv1 = bA.y, bv2 = bB.x, bv3 = bB.y;
            ffma2(acc[0][0], av0, bv0); ffma2(acc[0][1], av0, bv1);
            ffma2(acc[0][2], av0, bv2); ffma2(acc[0][3], av0, bv3);
            ffma2(acc[1][0], av1, bv0); ffma2(acc[1][1], av1, bv1);
            ffma2(acc[1][2], av1, bv2); ffma2(acc[1][3], av1, bv3);
            ffma2(acc[2][0], av2, bv0); ffma2(acc[2][1], av2, bv1);
            ffma2(acc[2][2], av2, bv2); ffma2(acc[2][3], av2, bv3);
            ffma2(acc[3][0], av3, bv0); ffma2(acc[3][1], av3, bv1);
            ffma2(acc[3][2], av3, bv2); ffma2(acc[3][3], av3, bv3);
        }
        if (more) {
            stage(buf ^ 1);
            __syncthreads();
            buf ^= 1;
        }
    }

    // epilogue
#pragma unroll
    for (int p = 0; p < 4; ++p) {
#pragma unroll
        for (int rr = 0; rr < 2; ++rr) {
            const int m = bm + (ty << 3) + (p << 1) + rr;
            if (m < M) {
#pragma unroll
                for (int j = 0; j < 4; ++j) {
                    const int n = bn + (tx << 2) + j;
                    if (n < N) {
                        float v = rr ? ull_hi(acc[p][j]) : ull_lo(acc[p][j]);
                        if constexpr (HAS_BIAS) v += bias[n];
                        if constexpr (RES_MODE == 1) v += R[(size_t)m * N + n];
                        if constexpr (RES_MODE == 2) v += preluf(R[(size_t)m * N + n], a_ep);
                        if constexpr (EPI_PRELU) v = preluf(v, a_ep);
                        C[(size_t)m * N + n] = v;
                    }
                }
            }
        }
    }
}

// ---------------- launch ----------------
extern "C" void kernel_launch(void* const* d_in, const int* in_sizes, int n_in,
                              void* d_out, int out_size)
{
    (void)in_sizes; (void)n_in; (void)out_size;

    const float* features  = (const float*)d_in[0];
    const float* label_emb = (const float*)d_in[1];
    const float* wa        = (const float*)d_in[2];
    const float* ba        = (const float*)d_in[3];
    const float* w0        = (const float*)d_in[4];
    const float* b0        = (const float*)d_in[5];
    const float* wg1       = (const float*)d_in[6];
    const float* wg2       = (const float*)d_in[7];
    const float* w_last    = (const float*)d_in[8];
    const float* b_last    = (const float*)d_in[9];
    const float* a_out     = (const float*)d_in[10];
    const float* wl0       = (const float*)d_in[11];
    const float* bl0       = (const float*)d_in[12];
    const float* wl1       = (const float*)d_in[13];
    const float* bl1       = (const float*)d_in[14];
    const float* wl2       = (const float*)d_in[15];
    const float* bl2       = (const float*)d_in[16];
    const float* wl3       = (const float*)d_in[17];
    const float* bl3       = (const float*)d_in[18];
    const float* a_lab     = (const float*)d_in[19];

    float *right, *x1, *x2, *x3, *xout;
    cudaGetSymbolAddress((void**)&right, g_right);
    cudaGetSymbolAddress((void**)&x1, g_x1);
    cudaGetSymbolAddress((void**)&x2, g_x2);
    cudaGetSymbolAddress((void**)&x3, g_x3);
    cudaGetSymbolAddress((void**)&xout, g_xout);

    // 1) fused attention -> right [N, F]
    attn_kernel<<<(N_DIM + 3) / 4, 128>>>(features, wa, ba, right);

    auto grid = [](int M, int N) { return dim3((unsigned)((N + 63) / 64), (unsigned)((M + 127) / 128)); };
    dim3 blk(256);

    // 2) x1 = right @ w0 + b0           (h0)
    gemm_k<0, 1, 0, 0><<<grid(N_DIM, HID_DIM), blk>>>(
        right, nullptr, w0, b0, nullptr, x1, N_DIM, HID_DIM, F_DIM, nullptr, nullptr);

    // 3) x2 = support(x1, x1) @ wg1 + prelu(x1)
    gemm_k<2, 0, 0, 2><<<grid(N_DIM, HID_DIM), blk>>>(
        x1, x1, wg1, nullptr, x1, x2, N_DIM, HID_DIM, HID_DIM, a_out, a_out);

    // 4) x3 = support(x2, x1) @ wg2 + prelu(x2)
    gemm_k<2, 0, 0, 2><<<grid(N_DIM, HID_DIM), blk>>>(
        x2, x1, wg2, nullptr, x2, x3, N_DIM, HID_DIM, HID_DIM, a_out, a_out);

    // 5) xout = prelu(x3) @ w_last + b_last
    gemm_k<1, 1, 0, 0><<<grid(N_DIM, C_DIM), blk>>>(
        x3, nullptr, w_last, b_last, nullptr, xout, N_DIM, C_DIM, HID_DIM, a_out, nullptr);

    // 6) y0 = prelu(label_emb @ wl0 + bl0)   -> x1
    gemm_k<0, 1, 1, 0><<<grid(N_DIM, HID_DIM), blk>>>(
        label_emb, nullptr, wl0, bl0, nullptr, x1, N_DIM, HID_DIM, C_DIM, nullptr, a_lab);

    // 7) y1 = prelu(y0 @ wl1 + bl1)          -> x2
    gemm_k<0, 1, 1, 0><<<grid(N_DIM, HID_DIM), blk>>>(
        x1, nullptr, wl1, bl1, nullptr, x2, N_DIM, HID_DIM, HID_DIM, nullptr, a_lab);

    // 8) y2 = prelu(y1 @ wl2 + bl2)          -> x1
    gemm_k<0, 1, 1, 0><<<grid(N_DIM, HID_DIM), blk>>>(
        x2, nullptr, wl2, bl2, nullptr, x1, N_DIM, HID_DIM, HID_DIM, nullptr, a_lab);

    // 9) out = y2 @ wl3 + bl3 + xout         -> d_out
    gemm_k<0, 1, 0, 1><<<grid(N_DIM, C_DIM), blk>>>(
        x1, nullptr, wl3, bl3, xout, (float*)d_out, N_DIM, C_DIM, HID_DIM, nullptr, nullptr);
}

// round 5
// speedup vs baseline: 1.2716x; 1.2716x over previous
#include <cuda_runtime.h>

#define H_DIM 10
#define N_DIM 100000
#define F_DIM 256
#define HID_DIM 512
#define C_DIM 47

// ---------------- scratch (device globals: no allocation allowed) ----------------
__device__ float g_right[(size_t)N_DIM * F_DIM];   // 102.4 MB
__device__ float g_x1[(size_t)N_DIM * HID_DIM];    // 204.8 MB  (h0 / y0 / y2)
__device__ float g_x2[(size_t)N_DIM * HID_DIM];    // 204.8 MB  (x2 / y1)
__device__ float g_x3[(size_t)N_DIM * HID_DIM];    // 204.8 MB  (x3)
__device__ float g_xout[(size_t)N_DIM * C_DIM];    // 18.8 MB

// ---------------- helpers ----------------
__device__ __forceinline__ float lrelu02(float x) { return x >= 0.f ? x : 0.2f * x; }
__device__ __forceinline__ float preluf(float x, float a) { return x >= 0.f ? x : a * x; }

__device__ __forceinline__ void ffma2(unsigned long long& acc,
                                      unsigned long long a,
                                      unsigned long long b) {
    asm("fma.rn.f32x2 %0, %1, %2, %0;" : "+l"(acc) : "l"(a), "l"(b));
}
__device__ __forceinline__ float ull_lo(unsigned long long u) {
    return __uint_as_float((unsigned)u);
}
__device__ __forceinline__ float ull_hi(unsigned long long u) {
    return __uint_as_float((unsigned)(u >> 32));
}
__device__ __forceinline__ unsigned long long dupf(float x) {
    unsigned u = __float_as_uint(x);
    return ((unsigned long long)u << 32) | u;
}

// ---------------- fused attention: one pass over features ----------------
__global__ __launch_bounds__(128)
void attn_kernel(const float* __restrict__ feat,
                 const float* __restrict__ wa,
                 const float* __restrict__ ba_p,
                 float* __restrict__ right)
{
    const int warp = threadIdx.x >> 5;
    const int lane = threadIdx.x & 31;
    const int n = blockIdx.x * 4 + warp;
    if (n >= N_DIM) return;

    const float4* wa4 = reinterpret_cast<const float4*>(wa);
    const float4 wl_a = wa4[lane];
    const float4 wl_b = wa4[32 + lane];
    const float4 wr_a = wa4[64 + lane];
    const float4 wr_b = wa4[96 + lane];
    const float ba = *ba_p;

    float4 fa[H_DIM], fb[H_DIM];
    float xl[H_DIM], xr[H_DIM];

#pragma unroll
    for (int h = 0; h < H_DIM; ++h) {
        const float4* f4 = reinterpret_cast<const float4*>(
            feat + ((size_t)h * N_DIM + (size_t)n) * F_DIM);
        fa[h] = f4[lane];
        fb[h] = f4[32 + lane];
        float dl = fa[h].x * wl_a.x + fa[h].y * wl_a.y + fa[h].z * wl_a.z + fa[h].w * wl_a.w
                 + fb[h].x * wl_b.x + fb[h].y * wl_b.y + fb[h].z * wl_b.z + fb[h].w * wl_b.w;
        float dr = fa[h].x * wr_a.x + fa[h].y * wr_a.y + fa[h].z * wr_a.z + fa[h].w * wr_a.w
                 + fb[h].x * wr_b.x + fb[h].y * wr_b.y + fb[h].z * wr_b.z + fb[h].w * wr_b.w;
#pragma unroll
        for (int off = 16; off; off >>= 1) {
            dl += __shfl_xor_sync(0xffffffffu, dl, off);
            dr += __shfl_xor_sync(0xffffffffu, dr, off);
        }
        xl[h] = dl;
        xr[h] = dr;
    }

    float sc[H_DIM];
    sc[0] = lrelu02(xl[0] + xr[0] + ba);
#pragma unroll
    for (int i = 1; i < H_DIM; ++i) {
        float mx = sc[0];
#pragma unroll
        for (int j = 1; j < i; ++j) mx = fmaxf(mx, sc[j]);
        float s = 0.f, accv = 0.f;
#pragma unroll
        for (int j = 0; j < i; ++j) {
            float e = __expf(sc[j] - mx);
            s += e;
            accv += e * xl[j];
        }
        sc[i] = lrelu02(accv / s + xr[i] + ba);
    }

    float mx = sc[0];
#pragma unroll
    for (int j = 1; j < H_DIM; ++j) mx = fmaxf(mx, sc[j]);
    float s = 0.f;
    float4 ra = make_float4(0.f, 0.f, 0.f, 0.f);
    float4 rb = make_float4(0.f, 0.f, 0.f, 0.f);
#pragma unroll
    for (int h = 0; h < H_DIM; ++h) {
        float e = __expf(sc[h] - mx);
        s += e;
        ra.x += e * fa[h].x; ra.y += e * fa[h].y; ra.z += e * fa[h].z; ra.w += e * fa[h].w;
        rb.x += e * fb[h].x; rb.y += e * fb[h].y; rb.z += e * fb[h].z; rb.w += e * fb[h].w;
    }
    float inv = 1.f / s;
    ra.x *= inv; ra.y *= inv; ra.z *= inv; ra.w *= inv;
    rb.x *= inv; rb.y *= inv; rb.z *= inv; rb.w *= inv;

    float4* out4 = reinterpret_cast<float4*>(right + (size_t)n * F_DIM);
    out4[lane] = ra;
    out4[32 + lane] = rb;
}

// ---------------- fused GEMM (fp32 SIMT, f32x2 FMA, A duplicated in smem) ----------
// C[m,n] = epi( in(A)[m,:] @ W[:,n] )
// IN_MODE:  0 = A        1 = prelu(A,a_in)       2 = 0.5*(prelu(A,a_in)+H0)
// RES_MODE: 0 = none     1 = +R[m,n]             2 = +prelu(R[m,n],a_ep)
// HAS_BIAS: +bias[n];  EPI_PRELU: prelu(result,a_ep) at the end
template<int IN_MODE, int HAS_BIAS, int EPI_PRELU, int RES_MODE>
__global__ __launch_bounds__(256)
void gemm_k(const float* __restrict__ A, const float* __restrict__ Hh,
            const float* __restrict__ W, const float* __restrict__ bias,
            const float* __restrict__ R, float* __restrict__ C,
            int M, int N, int K,
            const float* __restrict__ a_in_p, const float* __restrict__ a_ep_p)
{
    constexpr int BM = 128, BN = 128, BK = 8;
    // A stored duplicated along m (each value twice) -> f32x2 operand (m,m).
    // A reads are warp-broadcast, so duplication is crossbar-free.
    __shared__ __align__(16) float As[2][BK][2 * BM + 8];
    __shared__ __align__(16) float Bs[2][BK][BN];

    const int tid = threadIdx.x;
    const int bm = blockIdx.y * BM;
    const int bn = blockIdx.x * BN;

    float a_in = 0.f, a_ep = 0.f;
    if constexpr (IN_MODE >= 1) a_in = *a_in_p;
    if constexpr (EPI_PRELU || RES_MODE == 2) a_ep = *a_ep_p;

    // global-load assignments (one float4 of A, one float4 of B per thread per tile)
    const int ar  = tid >> 1;          // A row within tile (0..127)
    const int ak  = (tid & 1) << 2;    // A k-offset (0 or 4)
    const int bk  = tid >> 5;          // B k (0..7)
    const int bn0 = (tid & 31) << 2;   // B col offset (0..124)

    const bool kvec = (K & 3) == 0;
    const bool nvec = (N & 3) == 0;

    float4 aR, bR;

    auto loadAB = [&](int kt) {
        {
            int row = bm + ar;
            int k = kt + ak;
            float4 v  = make_float4(0.f, 0.f, 0.f, 0.f);
            float4 hv = make_float4(0.f, 0.f, 0.f, 0.f);
            if (row < M && k < K) {
                const float* p = A + (size_t)row * K + k;
                if (kvec) {
                    v = *reinterpret_cast<const float4*>(p);
                } else {
                    v.x = p[0];
                    if (k + 1 < K) v.y = p[1];
                    if (k + 2 < K) v.z = p[2];
                    if (k + 3 < K) v.w = p[3];
                }
                if constexpr (IN_MODE == 2) {
                    const float* q = Hh + (size_t)row * K + k;
                    if (kvec) {
                        hv = *reinterpret_cast<const float4*>(q);
                    } else {
                        hv.x = q[0];
                        if (k + 1 < K) hv.y = q[1];
                        if (k + 2 < K) hv.z = q[2];
                        if (k + 3 < K) hv.w = q[3];
                    }
                }
            }
            if constexpr (IN_MODE == 1) {
                v.x = preluf(v.x, a_in); v.y = preluf(v.y, a_in);
                v.z = preluf(v.z, a_in); v.w = preluf(v.w, a_in);
            } else if constexpr (IN_MODE == 2) {
                v.x = 0.5f * (preluf(v.x, a_in) + hv.x);
                v.y = 0.5f * (preluf(v.y, a_in) + hv.y);
                v.z = 0.5f * (preluf(v.z, a_in) + hv.z);
                v.w = 0.5f * (preluf(v.w, a_in) + hv.w);
            }
            aR = v;
        }
        {
            int k = kt + bk;
            int n = bn + bn0;
            float4 v = make_float4(0.f, 0.f, 0.f, 0.f);
            if (k < K && n < N) {
                const float* p = W + (size_t)k * N + n;
                if (nvec) {
                    v = *reinterpret_cast<const float4*>(p);
                } else {
                    v.x = p[0];
                    if (n + 1 < N) v.y = p[1];
                    if (n + 2 < N) v.z = p[2];
                    if (n + 3 < N) v.w = p[3];
                }
            }
            bR = v;
        }
    };

    auto stage = [&](int buf) {
        // A duplicated: row k, ull slot ar holds (v, v)
        reinterpret_cast<unsigned long long*>(As[buf][ak + 0])[ar] = dupf(aR.x);
        reinterpret_cast<unsigned long long*>(As[buf][ak + 1])[ar] = dupf(aR.y);
        reinterpret_cast<unsigned long long*>(As[buf][ak + 2])[ar] = dupf(aR.z);
        reinterpret_cast<unsigned long long*>(As[buf][ak + 3])[ar] = dupf(aR.w);
        *reinterpret_cast<float4*>(&Bs[buf][bk][bn0]) = bR;
    };

    const int ty = tid >> 4;   // 0..15 -> rows bm + ty*8 .. +7
    const int tx = tid & 15;   // cols: bn + tx*4 (+0..3) and bn + 64 + tx*4 (+0..3)

    unsigned long long acc[8][4];
#pragma unroll
    for (int i = 0; i < 8; ++i)
#pragma unroll
        for (int j = 0; j < 4; ++j) acc[i][j] = 0ull;

    const int tiles = (K + BK - 1) / BK;
    loadAB(0);
    stage(0);
    __syncthreads();

    int buf = 0;
    for (int t = 0; t < tiles; ++t) {
        const bool more = (t + 1 < tiles);
        if (more) loadAB((t + 1) * BK);
#pragma unroll
        for (int k = 0; k < BK; ++k) {
            const ulonglong2* ap =
                reinterpret_cast<const ulonglong2*>(&As[buf][k][ty << 4]);
            ulonglong2 a01 = ap[0], a23 = ap[1], a45 = ap[2], a67 = ap[3];
            ulonglong2 b01 = *reinterpret_cast<const ulonglong2*>(&Bs[buf][k][tx << 2]);
            ulonglong2 b23 = *reinterpret_cast<const ulonglong2*>(&Bs[buf][k][(tx << 2) + 64]);
            unsigned long long av[8] = {a01.x, a01.y, a23.x, a23.y,
                                        a45.x, a45.y, a67.x, a67.y};
#pragma unroll
            for (int i = 0; i < 8; ++i) {
                ffma2(acc[i][0], av[i], b01.x);
                ffma2(acc[i][1], av[i], b01.y);
                ffma2(acc[i][2], av[i], b23.x);
                ffma2(acc[i][3], av[i], b23.y);
            }
        }
        if (more) {
            stage(buf ^ 1);
            __syncthreads();
            buf ^= 1;
        }
    }

    // ---------------- epilogue ----------------
#pragma unroll
    for (int i = 0; i < 8; ++i) {
        const int m = bm + (ty << 3) + i;
        if (m >= M) continue;
#pragma unroll
        for (int g = 0; g < 2; ++g) {
            const int n0 = bn + (g << 6) + (tx << 2);
            float f0 = ull_lo(acc[i][2 * g]);
            float f1 = ull_hi(acc[i][2 * g]);
            float f2 = ull_lo(acc[i][2 * g + 1]);
            float f3 = ull_hi(acc[i][2 * g + 1]);
            if (nvec && n0 + 3 < N) {
                if constexpr (HAS_BIAS) {
                    float4 bv = *reinterpret_cast<const float4*>(bias + n0);
                    f0 += bv.x; f1 += bv.y; f2 += bv.z; f3 += bv.w;
                }
                if constexpr (RES_MODE == 1) {
                    float4 rv = *reinterpret_cast<const float4*>(R + (size_t)m * N + n0);
                    f0 += rv.x; f1 += rv.y; f2 += rv.z; f3 += rv.w;
                } else if constexpr (RES_MODE == 2) {
                    float4 rv = *reinterpret_cast<const float4*>(R + (size_t)m * N + n0);
                    f0 += preluf(rv.x, a_ep); f1 += preluf(rv.y, a_ep);
                    f2 += preluf(rv.z, a_ep); f3 += preluf(rv.w, a_ep);
                }
                if constexpr (EPI_PRELU) {
                    f0 = preluf(f0, a_ep); f1 = preluf(f1, a_ep);
                    f2 = preluf(f2, a_ep); f3 = preluf(f3, a_ep);
                }
                *reinterpret_cast<float4*>(C + (size_t)m * N + n0) =
                    make_float4(f0, f1, f2, f3);
            } else {
                float f[4] = {f0, f1, f2, f3};
#pragma unroll
                for (int j = 0; j < 4; ++j) {
                    const int n = n0 + j;
                    if (n < N) {
                        float v = f[j];
                        if constexpr (HAS_BIAS) v += bias[n];
                        if constexpr (RES_MODE == 1) v += R[(size_t)m * N + n];
                        if constexpr (RES_MODE == 2) v += preluf(R[(size_t)m * N + n], a_ep);
                        if constexpr (EPI_PRELU) v = preluf(v, a_ep);
                        C[(size_t)m * N + n] = v;
                    }
                }
            }
        }
    }
}

// ---------------- launch ----------------
extern "C" void kernel_launch(void* const* d_in, const int* in_sizes, int n_in,
                              void* d_out, int out_size)
{
    (void)in_sizes; (void)n_in; (void)out_size;

    const float* features  = (const float*)d_in[0];
    const float* label_emb = (const float*)d_in[1];
    const float* wa        = (const float*)d_in[2];
    const float* ba        = (const float*)d_in[3];
    const float* w0        = (const float*)d_in[4];
    const float* b0        = (const float*)d_in[5];
    const float* wg1       = (const float*)d_in[6];
    const float* wg2       = (const float*)d_in[7];
    const float* w_last    = (const float*)d_in[8];
    const float* b_last    = (const float*)d_in[9];
    const float* a_out     = (const float*)d_in[10];
    const float* wl0       = (const float*)d_in[11];
    const float* bl0       = (const float*)d_in[12];
    const float* wl1       = (const float*)d_in[13];
    const float* bl1       = (const float*)d_in[14];
    const float* wl2       = (const float*)d_in[15];
    const float* bl2       = (const float*)d_in[16];
    const float* wl3       = (const float*)d_in[17];
    const float* bl3       = (const float*)d_in[18];
    const float* a_lab     = (const float*)d_in[19];

    float *right, *x1, *x2, *x3, *xout;
    cudaGetSymbolAddress((void**)&right, g_right);
    cudaGetSymbolAddress((void**)&x1, g_x1);
    cudaGetSymbolAddress((void**)&x2, g_x2);
    cudaGetSymbolAddress((void**)&x3, g_x3);
    cudaGetSymbolAddress((void**)&xout, g_xout);

    // 1) fused attention -> right [N, F]
    attn_kernel<<<(N_DIM + 3) / 4, 128>>>(features, wa, ba, right);

    auto grid = [](int M, int N) { return dim3((unsigned)((N + 127) / 128), (unsigned)((M + 127) / 128)); };
    dim3 blk(256);

    // 2) x1 = right @ w0 + b0           (h0)
    gemm_k<0, 1, 0, 0><<<grid(N_DIM, HID_DIM), blk>>>(
        right, nullptr, w0, b0, nullptr, x1, N_DIM, HID_DIM, F_DIM, nullptr, nullptr);

    // 3) x2 = support(x1, x1) @ wg1 + prelu(x1)
    gemm_k<2, 0, 0, 2><<<grid(N_DIM, HID_DIM), blk>>>(
        x1, x1, wg1, nullptr, x1, x2, N_DIM, HID_DIM, HID_DIM, a_out, a_out);

    // 4) x3 = support(x2, x1) @ wg2 + prelu(x2)
    gemm_k<2, 0, 0, 2><<<grid(N_DIM, HID_DIM), blk>>>(
        x2, x1, wg2, nullptr, x2, x3, N_DIM, HID_DIM, HID_DIM, a_out, a_out);

    // 5) xout = prelu(x3) @ w_last + b_last
    gemm_k<1, 1, 0, 0><<<grid(N_DIM, C_DIM), blk>>>(
        x3, nullptr, w_last, b_last, nullptr, xout, N_DIM, C_DIM, HID_DIM, a_out, nullptr);

    // 6) y0 = prelu(label_emb @ wl0 + bl0)   -> x1
    gemm_k<0, 1, 1, 0><<<grid(N_DIM, HID_DIM), blk>>>(
        label_emb, nullptr, wl0, bl0, nullptr, x1, N_DIM, HID_DIM, C_DIM, nullptr, a_lab);

    // 7) y1 = prelu(y0 @ wl1 + bl1)          -> x2
    gemm_k<0, 1, 1, 0><<<grid(N_DIM, HID_DIM), blk>>>(
        x1, nullptr, wl1, bl1, nullptr, x2, N_DIM, HID_DIM, HID_DIM, nullptr, a_lab);

    // 8) y2 = prelu(y1 @ wl2 + bl2)          -> x1
    gemm_k<0, 1, 1, 0><<<grid(N_DIM, HID_DIM), blk>>>(
        x2, nullptr, wl2, bl2, nullptr, x1, N_DIM, HID_DIM, HID_DIM, nullptr, a_lab);

    // 9) out = y2 @ wl3 + bl3 + xout         -> d_out
    gemm_k<0, 1, 0, 1><<<grid(N_DIM, C_DIM), blk>>>(
        x1, nullptr, wl3, bl3, xout, (float*)d_out, N_DIM, C_DIM, HID_DIM, nullptr, nullptr);
}